// round 10
// baseline (speedup 1.0000x reference)
#include <cuda_runtime.h>
#include <cuda_bf16.h>
#include <cstdint>
#include <math.h>

#define CC   512
#define HW   4096
#define BB   4
#define GG   32
#define CPG  16
#define EPSV 1e-5f

typedef __nv_bfloat16  bf16;
typedef __nv_bfloat162 bf162;

// ------------------------------------------------------------------
// scratch
// ------------------------------------------------------------------
__device__ bf16  g_h[(size_t)BB * HW * CC];        // h^T    [b, n, c]
__device__ bf16  g_qkv[(size_t)BB * HW * 3 * CC];  // q|k|v'' packed [b, n, 1536]
__device__ bf16  g_p[(size_t)BB * HW * HW];        // unnormalized probs e^s (bf16)
__device__ bf16  g_w[4][(size_t)CC * CC];          // bf16: Wq, Wk, W'(=Wp@Wv), Wp
__device__ bf16  g_wv[(size_t)CC * CC];            // bf16 Wv (input to W' prep)
__device__ float g_qkvb[3 * CC];                   // concat(q_b, k_b, cb)

// ------------------------------------------------------------------
// helpers
// ------------------------------------------------------------------
__device__ __forceinline__ uint32_t smem_to_u32(const void* p) {
    uint32_t a;
    asm("{ .reg .u64 t; cvta.to.shared.u64 t, %1; cvt.u32.u64 %0, t; }"
        : "=r"(a) : "l"(p));
    return a;
}

#define SWZ(o) ((o) ^ (((o) >> 3) & 0x70))

__device__ __forceinline__ void cpasync16(uint32_t dst, const void* src) {
    asm volatile("cp.async.cg.shared.global [%0], [%1], 16;" :: "r"(dst), "l"(src));
}
#define CP_COMMIT() asm volatile("cp.async.commit_group;" ::: "memory")
#define CP_WAIT1()  asm volatile("cp.async.wait_group 1;" ::: "memory")

__device__ __forceinline__ void ldsm4(uint32_t& r0, uint32_t& r1, uint32_t& r2,
                                      uint32_t& r3, uint32_t addr) {
    asm volatile("ldmatrix.sync.aligned.m8n8.x4.shared.b16 {%0,%1,%2,%3}, [%4];"
                 : "=r"(r0), "=r"(r1), "=r"(r2), "=r"(r3) : "r"(addr));
}

__device__ __forceinline__ void ldsm4t(uint32_t& r0, uint32_t& r1, uint32_t& r2,
                                       uint32_t& r3, uint32_t addr) {
    asm volatile("ldmatrix.sync.aligned.m8n8.x4.trans.shared.b16 {%0,%1,%2,%3}, [%4];"
                 : "=r"(r0), "=r"(r1), "=r"(r2), "=r"(r3) : "r"(addr));
}

__device__ __forceinline__ void mma_bf16(float c[4], uint32_t a0, uint32_t a1,
                                         uint32_t a2, uint32_t a3,
                                         uint32_t b0, uint32_t b1) {
    asm volatile(
        "mma.sync.aligned.m16n8k16.row.col.f32.bf16.bf16.f32 "
        "{%0,%1,%2,%3}, {%4,%5,%6,%7}, {%8,%9}, {%0,%1,%2,%3};"
        : "+f"(c[0]), "+f"(c[1]), "+f"(c[2]), "+f"(c[3])
        : "r"(a0), "r"(a1), "r"(a2), "r"(a3), "r"(b0), "r"(b1));
}

__device__ __forceinline__ void sts_f32(uint32_t a, float v) {
    asm volatile("st.shared.f32 [%0], %1;" :: "r"(a), "f"(v));
}
__device__ __forceinline__ float4 lds_f128(uint32_t a) {
    float4 v;
    asm volatile("ld.shared.v4.f32 {%0,%1,%2,%3}, [%4];"
                 : "=f"(v.x), "=f"(v.y), "=f"(v.z), "=f"(v.w) : "r"(a));
    return v;
}

// ------------------------------------------------------------------
// convert weights fp32 -> bf16 (Wv into spare buffer); q/k bias
// ------------------------------------------------------------------
__global__ __launch_bounds__(256) void cvtw_kernel(const float* __restrict__ q,
                                                   const float* __restrict__ k,
                                                   const float* __restrict__ v,
                                                   const float* __restrict__ p,
                                                   const float* __restrict__ qb,
                                                   const float* __restrict__ kb) {
    const int n = CC * CC;
    int i = blockIdx.x * 256 + threadIdx.x;
    if (i < 2 * CC)
        g_qkvb[i] = (i < CC) ? qb[i] : kb[i - CC];
    if (i >= 4 * n) return;
    const int seg = i / n, j = i % n;
    if (seg == 0)      g_w[0][j] = __float2bfloat16_rn(q[j]);
    else if (seg == 1) g_w[1][j] = __float2bfloat16_rn(k[j]);
    else if (seg == 2) g_wv[j]   = __float2bfloat16_rn(v[j]);
    else               g_w[3][j] = __float2bfloat16_rn(p[j]);
}

// ------------------------------------------------------------------
// cb[c] = pb[c] + sum_c' Wp[c,c'] * vb[c']
// ------------------------------------------------------------------
__global__ __launch_bounds__(256) void prepb_kernel(const float* __restrict__ pw,
                                                    const float* __restrict__ vbv,
                                                    const float* __restrict__ pbv) {
    int c = blockIdx.x * 256 + threadIdx.x;
    if (c >= CC) return;
    float s = pbv[c];
    const float* row = pw + (size_t)c * CC;
    #pragma unroll 8
    for (int j = 0; j < CC; j++) s += row[j] * vbv[j];
    g_qkvb[2 * CC + c] = s;
}

// ------------------------------------------------------------------
// GroupNorm -> transposed h^T [b, n, c], bf16 (512 threads)
// ------------------------------------------------------------------
__global__ __launch_bounds__(512) void gn_kernel(const float* __restrict__ x,
                                                 const float* __restrict__ w,
                                                 const float* __restrict__ bgn) {
    __shared__ float ts[CPG][513];
    __shared__ float rs[512], rq[512];
    const int bg = blockIdx.x;
    const int b = bg / GG, g = bg % GG;
    const float* xp = x + ((size_t)b * CC + (size_t)g * CPG) * HW;
    const int N = CPG * HW;
    const int t = threadIdx.x;

    float s = 0.f, ss = 0.f;
    for (int i = t; i < N; i += 512) {
        float v = xp[i];
        s += v; ss += v * v;
    }
    rs[t] = s; rq[t] = ss;
    __syncthreads();
    #pragma unroll
    for (int o = 256; o > 0; o >>= 1) {
        if (t < o) { rs[t] += rs[t + o]; rq[t] += rq[t + o]; }
        __syncthreads();
    }
    const float mean = rs[0] * (1.0f / N);
    const float var  = rq[0] * (1.0f / N) - mean * mean;
    const float rinv = rsqrtf(var + EPSV);

    float scl[CPG], sft[CPG];
    #pragma unroll
    for (int c = 0; c < CPG; c++) {
        float wc = w[g * CPG + c];
        scl[c] = rinv * wc;
        sft[c] = bgn[g * CPG + c] - mean * rinv * wc;
    }

    for (int n0 = 0; n0 < HW; n0 += 512) {
        __syncthreads();
        #pragma unroll
        for (int c = 0; c < CPG; c++) ts[c][t] = xp[(size_t)c * HW + n0 + t];
        __syncthreads();
        bf16* hp = g_h + ((size_t)b * HW + n0 + t) * CC + g * CPG;
        #pragma unroll
        for (int c = 0; c < CPG; c += 2) {
            bf162 v;
            v.x = __float2bfloat16_rn(ts[c + 0][t] * scl[c + 0] + sft[c + 0]);
            v.y = __float2bfloat16_rn(ts[c + 1][t] * scl[c + 1] + sft[c + 1]);
            *(bf162*)&hp[c] = v;
        }
    }
}

// ------------------------------------------------------------------
// tiles: 128x128x64, 4 warps (2x2), 128 threads, 2 CTAs/SM, 3-stage cp.async
// ------------------------------------------------------------------
#define STAGES 3
#define A_BYTES 16384
#define B_BYTES 16384
#define STAGE_B (A_BYTES + B_BYTES)
#define SMEM_DYN (1024 + STAGES * STAGE_B)

__device__ __forceinline__ void load_tile(uint32_t slot, const bf16* __restrict__ g,
                                          int row0, int k0, int ld, int tid) {
    #pragma unroll
    for (int c = 0; c < 8; c++) {
        int chunk = tid + c * 128;
        int r  = chunk >> 3;
        int c8 = chunk & 7;
        uint32_t off = SWZ((uint32_t)(r * 128 + c8 * 16));
        cpasync16(slot + off, g + (size_t)(row0 + r) * ld + k0 + c8 * 8);
    }
}

// B row-major [K,N] tile: 64 k-rows x 128 n-cols, 2 col-blocks of 8KB
__device__ __forceinline__ void load_tileT(uint32_t slot, const bf16* __restrict__ g,
                                           int n0, int k0, int ld, int tid) {
    #pragma unroll
    for (int c = 0; c < 8; c++) {
        int chunk = tid + c * 128;
        int r = chunk >> 4;
        int u = chunk & 15;
        uint32_t off = (uint32_t)(u >> 3) * 8192u + SWZ((uint32_t)(r * 128 + (u & 7) * 16));
        cpasync16(slot + off, g + (size_t)(k0 + r) * ld + n0 + u * 8);
    }
}

// ------------------------------------------------------------------
// generic GEMM: D = A[M,K].B^T (BTRANS=0: B[N,K]; BTRANS=1: B[K,N] row-major)
// EXPF: D = exp(alpha*D)
// ------------------------------------------------------------------
template <bool SCALE, bool COLB, bool OUTBF, bool EXPF, bool BTRANS>
__global__ __launch_bounds__(128, 2) void mm_kernel(
    const bf16* __restrict__ A, int lda, const bf16* __restrict__ B, int ldb,
    void* __restrict__ Cv,
    int M, int N, int K, long sA, long sB, long sC,
    const float* __restrict__ bias, float alpha)
{
    extern __shared__ char smraw[];
    const uint32_t sb = (smem_to_u32(smraw) + 1023u) & ~1023u;

    const int tid = threadIdx.x, lane = tid & 31, wid = tid >> 5;
    const int wm = wid >> 1;
    const int wn = wid & 1;
    const int bm = blockIdx.y * 128, bn = blockIdx.x * 128, z = blockIdx.z;
    A += (size_t)z * sA;
    B += (size_t)z * sB;

    float c[4][8][4];
    #pragma unroll
    for (int i = 0; i < 4; i++)
        #pragma unroll
        for (int j = 0; j < 8; j++)
            #pragma unroll
            for (int r = 0; r < 4; r++) c[i][j][r] = 0.f;

    #pragma unroll
    for (int t = 0; t < STAGES - 1; t++) {
        load_tile(sb + t * STAGE_B, A, bm, t * 64, lda, tid);
        if (BTRANS) load_tileT(sb + t * STAGE_B + A_BYTES, B, bn, t * 64, ldb, tid);
        else        load_tile(sb + t * STAGE_B + A_BYTES, B, bn, t * 64, ldb, tid);
        CP_COMMIT();
    }

    const int nk = K >> 6;
    const int arow = lane & 15;
    const int akb  = (lane >> 4) * 16;
    const int brow = (lane & 7) | ((lane & 16) >> 1);
    const int bkb  = (lane & 8) << 1;
    const int trow = lane & 15;
    const int tnb  = (lane >> 4) * 16;

    for (int kt = 0; kt < nk; kt++) {
        CP_WAIT1();
        __syncthreads();

        const int tl = kt + STAGES - 1;
        if (tl < nk) {
            const int slot = tl % STAGES;
            load_tile(sb + slot * STAGE_B, A, bm, tl * 64, lda, tid);
            if (BTRANS) load_tileT(sb + slot * STAGE_B + A_BYTES, B, bn, tl * 64, ldb, tid);
            else        load_tile(sb + slot * STAGE_B + A_BYTES, B, bn, tl * 64, ldb, tid);
        }
        CP_COMMIT();

        const uint32_t aBase = sb + (kt % STAGES) * STAGE_B;
        const uint32_t bBase = aBase + A_BYTES;

        #pragma unroll
        for (int kb = 0; kb < 4; kb++) {
            uint32_t a[4][4];
            #pragma unroll
            for (int fm = 0; fm < 4; fm++) {
                uint32_t addr = aBase +
                    SWZ((uint32_t)((wm * 64 + fm * 16 + arow) * 128 + kb * 32 + akb));
                ldsm4(a[fm][0], a[fm][1], a[fm][2], a[fm][3], addr);
            }
            uint32_t b[4][4];
            #pragma unroll
            for (int fb = 0; fb < 4; fb++) {
                if (BTRANS) {
                    uint32_t addr = bBase + (uint32_t)wn * 8192u +
                        SWZ((uint32_t)((kb * 16 + trow) * 128 + fb * 32 + tnb));
                    ldsm4t(b[fb][0], b[fb][1], b[fb][2], b[fb][3], addr);
                } else {
                    uint32_t addr = bBase +
                        SWZ((uint32_t)((wn * 64 + fb * 16 + brow) * 128 + kb * 32 + bkb));
                    ldsm4(b[fb][0], b[fb][1], b[fb][2], b[fb][3], addr);
                }
            }
            #pragma unroll
            for (int fm = 0; fm < 4; fm++)
                #pragma unroll
                for (int fn = 0; fn < 8; fn++)
                    mma_bf16(c[fm][fn],
                             a[fm][0], a[fm][1], a[fm][2], a[fm][3],
                             b[fn >> 1][(fn & 1) * 2], b[fn >> 1][(fn & 1) * 2 + 1]);
        }
    }

    // ---------------- epilogue ----------------
    const int gid = lane >> 2, tig = lane & 3;

    #pragma unroll
    for (int fm = 0; fm < 4; fm++) {
        const int r0 = bm + wm * 64 + fm * 16 + gid;
        #pragma unroll
        for (int fn = 0; fn < 8; fn++) {
            const int col = bn + wn * 64 + fn * 8 + 2 * tig;
            float cb0 = COLB ? bias[col] : 0.f;
            float cb1 = COLB ? bias[col + 1] : 0.f;

            float2 v0, v1;
            v0.x = c[fm][fn][0]; v0.y = c[fm][fn][1];
            v1.x = c[fm][fn][2]; v1.y = c[fm][fn][3];
            if (SCALE) { v0.x *= alpha; v0.y *= alpha; v1.x *= alpha; v1.y *= alpha; }
            if (EXPF) {
                v0.x = __expf(v0.x); v0.y = __expf(v0.y);
                v1.x = __expf(v1.x); v1.y = __expf(v1.y);
            }
            if (COLB)  { v0.x += cb0; v0.y += cb1; v1.x += cb0; v1.y += cb1; }
            if (OUTBF) {
                bf16* Cb = (bf16*)Cv + (size_t)z * sC;
                bf162 w0, w1;
                w0.x = __float2bfloat16_rn(v0.x); w0.y = __float2bfloat16_rn(v0.y);
                w1.x = __float2bfloat16_rn(v1.x); w1.y = __float2bfloat16_rn(v1.y);
                *(bf162*)&Cb[(size_t)r0 * N + col] = w0;
                *(bf162*)&Cb[(size_t)(r0 + 8) * N + col] = w1;
            } else {
                float* Cb = (float*)Cv + (size_t)z * sC;
                *(float2*)&Cb[(size_t)r0 * N + col] = v0;
                *(float2*)&Cb[(size_t)(r0 + 8) * N + col] = v1;
            }
        }
    }
}

// ------------------------------------------------------------------
// AV final: out[c,i] = x[c,i] + (sum_j P[i,j] v''[j,c]) / (sum_j P[i,j])
// Normalized tile staged through smem, transposed, written coalesced.
// ------------------------------------------------------------------
#define OSM_STRIDE 528   // (128+4) floats * 4B, 16B aligned per col

__global__ __launch_bounds__(128, 2) void av_kernel(
    const bf16* __restrict__ A, int lda, const bf16* __restrict__ B, int ldb,
    float* __restrict__ out, const float* __restrict__ x, int K,
    long sA, long sB)
{
    extern __shared__ char smraw[];
    const uint32_t sb = (smem_to_u32(smraw) + 1023u) & ~1023u;

    const int tid = threadIdx.x, lane = tid & 31, wid = tid >> 5;
    const int wm = wid >> 1;
    const int wn = wid & 1;
    const int bm = blockIdx.y * 128, bn = blockIdx.x * 128, z = blockIdx.z;
    A += (size_t)z * sA;
    B += (size_t)z * sB;

    float c[4][8][4];
    #pragma unroll
    for (int i = 0; i < 4; i++)
        #pragma unroll
        for (int j = 0; j < 8; j++)
            #pragma unroll
            for (int r = 0; r < 4; r++) c[i][j][r] = 0.f;
    float rs[4][2];
    #pragma unroll
    for (int i = 0; i < 4; i++) { rs[i][0] = 0.f; rs[i][1] = 0.f; }

    #pragma unroll
    for (int t = 0; t < STAGES - 1; t++) {
        load_tile(sb + t * STAGE_B, A, bm, t * 64, lda, tid);
        load_tileT(sb + t * STAGE_B + A_BYTES, B, bn, t * 64, ldb, tid);
        CP_COMMIT();
    }

    const int nk = K >> 6;
    const int arow = lane & 15;
    const int akb  = (lane >> 4) * 16;
    const int trow = lane & 15;
    const int tnb  = (lane >> 4) * 16;

    for (int kt = 0; kt < nk; kt++) {
        CP_WAIT1();
        __syncthreads();

        const int tl = kt + STAGES - 1;
        if (tl < nk) {
            const int slot = tl % STAGES;
            load_tile(sb + slot * STAGE_B, A, bm, tl * 64, lda, tid);
            load_tileT(sb + slot * STAGE_B + A_BYTES, B, bn, tl * 64, ldb, tid);
        }
        CP_COMMIT();

        const uint32_t aBase = sb + (kt % STAGES) * STAGE_B;
        const uint32_t bBase = aBase + A_BYTES;

        #pragma unroll
        for (int kb = 0; kb < 4; kb++) {
            uint32_t a[4][4];
            #pragma unroll
            for (int fm = 0; fm < 4; fm++) {
                uint32_t addr = aBase +
                    SWZ((uint32_t)((wm * 64 + fm * 16 + arow) * 128 + kb * 32 + akb));
                ldsm4(a[fm][0], a[fm][1], a[fm][2], a[fm][3], addr);
            }
            #pragma unroll
            for (int fm = 0; fm < 4; fm++) {
                float2 t0 = __bfloat1622float2(*(bf162*)&a[fm][0]);
                float2 t1 = __bfloat1622float2(*(bf162*)&a[fm][1]);
                float2 t2 = __bfloat1622float2(*(bf162*)&a[fm][2]);
                float2 t3 = __bfloat1622float2(*(bf162*)&a[fm][3]);
                rs[fm][0] += (t0.x + t0.y) + (t2.x + t2.y);
                rs[fm][1] += (t1.x + t1.y) + (t3.x + t3.y);
            }
            uint32_t b[4][4];
            #pragma unroll
            for (int fb = 0; fb < 4; fb++) {
                uint32_t addr = bBase + (uint32_t)wn * 8192u +
                    SWZ((uint32_t)((kb * 16 + trow) * 128 + fb * 32 + tnb));
                ldsm4t(b[fb][0], b[fb][1], b[fb][2], b[fb][3], addr);
            }
            #pragma unroll
            for (int fm = 0; fm < 4; fm++)
                #pragma unroll
                for (int fn = 0; fn < 8; fn++)
                    mma_bf16(c[fm][fn],
                             a[fm][0], a[fm][1], a[fm][2], a[fm][3],
                             b[fn >> 1][(fn & 1) * 2], b[fn >> 1][(fn & 1) * 2 + 1]);
        }
    }

    // ---------------- epilogue: normalize -> smem transpose -> coalesced out --
    __syncthreads();                 // all smem reads of mainloop done
    const int gid = lane >> 2, tig = lane & 3;

    #pragma unroll
    for (int fm = 0; fm < 4; fm++) {
        float s0 = rs[fm][0];
        s0 += __shfl_xor_sync(0xffffffffu, s0, 1);
        s0 += __shfl_xor_sync(0xffffffffu, s0, 2);
        float s1 = rs[fm][1];
        s1 += __shfl_xor_sync(0xffffffffu, s1, 1);
        s1 += __shfl_xor_sync(0xffffffffu, s1, 2);
        const float inv0 = 1.0f / s0;
        const float inv1 = 1.0f / s1;
        const int rl = wm * 64 + fm * 16 + gid;       // local row (i)
        #pragma unroll
        for (int fn = 0; fn < 8; fn++) {
            const int cl = wn * 64 + fn * 8 + 2 * tig; // local col (c)
            sts_f32(sb + (uint32_t)cl * OSM_STRIDE + rl * 4,            c[fm][fn][0] * inv0);
            sts_f32(sb + (uint32_t)(cl + 1) * OSM_STRIDE + rl * 4,      c[fm][fn][1] * inv0);
            sts_f32(sb + (uint32_t)cl * OSM_STRIDE + (rl + 8) * 4,      c[fm][fn][2] * inv1);
            sts_f32(sb + (uint32_t)(cl + 1) * OSM_STRIDE + (rl + 8) * 4, c[fm][fn][3] * inv1);
        }
    }
    __syncthreads();

    float* Ob = out + (size_t)z * CC * HW;
    const float* Xb = x + (size_t)z * CC * HW;
    #pragma unroll
    for (int it = 0; it < 32; it++) {
        const int f  = tid + it * 128;        // float4 index in tile
        const int cl = f >> 5;                // 0..127 (c)
        const int i4 = f & 31;                // float4 along i
        float4 v = lds_f128(sb + (uint32_t)cl * OSM_STRIDE + i4 * 16);
        const size_t gidx = (size_t)(bn + cl) * HW + bm + i4 * 4;
        const float4 xr = *(const float4*)&Xb[gidx];
        v.x += xr.x; v.y += xr.y; v.z += xr.z; v.w += xr.w;
        *(float4*)&Ob[gidx] = v;
    }
}

// ------------------------------------------------------------------
// launch
// ------------------------------------------------------------------
extern "C" void kernel_launch(void* const* d_in, const int* in_sizes, int n_in,
                              void* d_out, int out_size) {
    const float* x   = (const float*)d_in[0];
    const float* gnw = (const float*)d_in[1];
    const float* gnb = (const float*)d_in[2];
    const float* qw  = (const float*)d_in[3];
    const float* qb  = (const float*)d_in[4];
    const float* kw  = (const float*)d_in[5];
    const float* kb  = (const float*)d_in[6];
    const float* vw  = (const float*)d_in[7];
    const float* vb  = (const float*)d_in[8];
    const float* pw  = (const float*)d_in[9];
    const float* pb  = (const float*)d_in[10];
    float* out = (float*)d_out;

    bf16 *h, *qkv, *p, *wb, *wv;
    float* qkvbv;
    cudaGetSymbolAddress((void**)&h,   g_h);
    cudaGetSymbolAddress((void**)&qkv, g_qkv);
    cudaGetSymbolAddress((void**)&p,   g_p);
    cudaGetSymbolAddress((void**)&wb,  g_w);
    cudaGetSymbolAddress((void**)&wv,  g_wv);
    cudaGetSymbolAddress((void**)&qkvbv, g_qkvb);
    bf16* qkvwb  = wb;                        // [Wq;Wk;W'] contiguous
    bf16* wprime = wb + 2 * (size_t)CC * CC;  // W' slot
    bf16* pwb    = wb + 3 * (size_t)CC * CC;  // Wp bf16

    cudaFuncSetAttribute(mm_kernel<false, true,  true,  false, false>, cudaFuncAttributeMaxDynamicSharedMemorySize, SMEM_DYN);
    cudaFuncSetAttribute(mm_kernel<true,  false, true,  true,  false>, cudaFuncAttributeMaxDynamicSharedMemorySize, SMEM_DYN);
    cudaFuncSetAttribute(mm_kernel<false, false, true,  false, true >, cudaFuncAttributeMaxDynamicSharedMemorySize, SMEM_DYN);
    cudaFuncSetAttribute(av_kernel, cudaFuncAttributeMaxDynamicSharedMemorySize, SMEM_DYN);

    const long sNC  = (long)HW * CC;
    const long sNC3 = (long)HW * 3 * CC;
    const long sNN  = (long)HW * HW;
    const float scale = 0.044194173824159216f;   // 512^-0.5

    // 0a. weights -> bf16 (Wv to spare), q/k bias
    cvtw_kernel<<<(4 * CC * CC + 255) / 256, 256>>>(qw, kw, vw, pw, qb, kb);
    // 0b. cb = Wp@vb + pb (fp32)
    prepb_kernel<<<(CC + 255) / 256, 256>>>(pw, vb, pb);
    // 0c. W' = Wp @ Wv (bf16 MMA, fp32 accum): M=N=K=512, B=Wv [K,N] row-major
    dim3 gW(CC / 128, CC / 128, 1);
    mm_kernel<false, false, true, false, true><<<gW, 128, SMEM_DYN>>>(
        pwb, CC, wv, CC, wprime, CC, CC, CC, 0, 0, 0, nullptr, 1.f);

    // 1. GroupNorm -> h^T [b, n, c] bf16
    gn_kernel<<<BB * GG, 512>>>(x, gnw, gnb);

    // 2. fused q|k|v'' [b, n, 1536]: M=HW, N=1536, K=CC; +col bias [qb;kb;cb]
    dim3 gQKV(1536 / 128, HW / 128, BB);
    mm_kernel<false, true, true, false, false><<<gQKV, 128, SMEM_DYN>>>(
        h, CC, qkvwb, CC, qkv, HW, 3 * CC, CC, sNC, 0, sNC3, qkvbv, 1.f);

    // 3. probs = exp(q.k * scale), unnormalized bf16
    dim3 gS(HW / 128, HW / 128, BB);
    mm_kernel<true, false, true, true, false><<<gS, 128, SMEM_DYN>>>(
        qkv, 3 * CC, qkv + CC, 3 * CC, p, HW, HW, CC, sNC3, sNC3, sNN,
        nullptr, scale);

    // 4. AV + normalize + residual -> final out [b, c, n] fp32
    dim3 gO(CC / 128, HW / 128, BB);
    av_kernel<<<gO, 128, SMEM_DYN>>>(
        p, HW, qkv + 2 * CC, 3 * CC, out, x, HW, sNN, sNC3);
}

// round 11
// speedup vs baseline: 1.1203x; 1.1203x over previous
#include <cuda_runtime.h>
#include <cuda_bf16.h>
#include <cstdint>
#include <math.h>

#define CC   512
#define HW   4096
#define BB   4
#define GG   32
#define CPG  16
#define EPSV 1e-5f

typedef __nv_bfloat16  bf16;
typedef __nv_bfloat162 bf162;

// ------------------------------------------------------------------
// scratch
// ------------------------------------------------------------------
__device__ bf16  g_h[(size_t)BB * HW * CC];        // h^T    [b, n, c]
__device__ bf16  g_qkv[(size_t)BB * HW * 3 * CC];  // q|k|v^T packed [b, n, 1536]
__device__ bf16  g_o[(size_t)BB * HW * CC];        // o^T    [b, n, c]
__device__ bf16  g_p[(size_t)BB * HW * HW];        // unnormalized probs e^s (bf16)
__device__ bf16  g_w[4][(size_t)CC * CC];          // bf16 weights q,k,v (contig) + p
__device__ float g_qkvb[3 * CC];                   // concat(q_b, k_b, v_b)
__device__ float g_scl[BB * CC];                   // GN per-channel scale
__device__ float g_sft[BB * CC];                   // GN per-channel shift

// ------------------------------------------------------------------
// helpers
// ------------------------------------------------------------------
__device__ __forceinline__ uint32_t smem_to_u32(const void* p) {
    uint32_t a;
    asm("{ .reg .u64 t; cvta.to.shared.u64 t, %1; cvt.u32.u64 %0, t; }"
        : "=r"(a) : "l"(p));
    return a;
}

#define SWZ(o) ((o) ^ (((o) >> 3) & 0x70))

__device__ __forceinline__ void cpasync16(uint32_t dst, const void* src) {
    asm volatile("cp.async.cg.shared.global [%0], [%1], 16;" :: "r"(dst), "l"(src));
}
#define CP_COMMIT() asm volatile("cp.async.commit_group;" ::: "memory")
#define CP_WAIT1()  asm volatile("cp.async.wait_group 1;" ::: "memory")

__device__ __forceinline__ void ldsm4(uint32_t& r0, uint32_t& r1, uint32_t& r2,
                                      uint32_t& r3, uint32_t addr) {
    asm volatile("ldmatrix.sync.aligned.m8n8.x4.shared.b16 {%0,%1,%2,%3}, [%4];"
                 : "=r"(r0), "=r"(r1), "=r"(r2), "=r"(r3) : "r"(addr));
}

__device__ __forceinline__ void ldsm4t(uint32_t& r0, uint32_t& r1, uint32_t& r2,
                                       uint32_t& r3, uint32_t addr) {
    asm volatile("ldmatrix.sync.aligned.m8n8.x4.trans.shared.b16 {%0,%1,%2,%3}, [%4];"
                 : "=r"(r0), "=r"(r1), "=r"(r2), "=r"(r3) : "r"(addr));
}

__device__ __forceinline__ void mma_bf16(float c[4], uint32_t a0, uint32_t a1,
                                         uint32_t a2, uint32_t a3,
                                         uint32_t b0, uint32_t b1) {
    asm volatile(
        "mma.sync.aligned.m16n8k16.row.col.f32.bf16.bf16.f32 "
        "{%0,%1,%2,%3}, {%4,%5,%6,%7}, {%8,%9}, {%0,%1,%2,%3};"
        : "+f"(c[0]), "+f"(c[1]), "+f"(c[2]), "+f"(c[3])
        : "r"(a0), "r"(a1), "r"(a2), "r"(a3), "r"(b0), "r"(b1));
}

// ------------------------------------------------------------------
// convert weights fp32 -> bf16; concat qkv bias
// ------------------------------------------------------------------
__global__ __launch_bounds__(256) void cvtw_kernel(const float* __restrict__ q,
                                                   const float* __restrict__ k,
                                                   const float* __restrict__ v,
                                                   const float* __restrict__ p,
                                                   const float* __restrict__ qb,
                                                   const float* __restrict__ kb,
                                                   const float* __restrict__ vb) {
    const int n = CC * CC;
    int i = blockIdx.x * 256 + threadIdx.x;
    if (i < 3 * CC)
        g_qkvb[i] = (i < CC) ? qb[i] : (i < 2 * CC) ? kb[i - CC] : vb[i - 2 * CC];
    if (i >= 4 * n) return;
    const int seg = i / n, j = i % n;
    const float* src = (seg == 0) ? q : (seg == 1) ? k : (seg == 2) ? v : p;
    g_w[seg][j] = __float2bfloat16_rn(src[j]);
}

// ------------------------------------------------------------------
// GroupNorm stats: one CTA per (b, g); emits per-channel scale/shift
// ------------------------------------------------------------------
__global__ __launch_bounds__(512) void gn_stats(const float* __restrict__ x,
                                                const float* __restrict__ w,
                                                const float* __restrict__ bgn) {
    __shared__ float rs[512], rq[512];
    const int bg = blockIdx.x;
    const int b = bg / GG, g = bg % GG;
    const float* xp = x + ((size_t)b * CC + (size_t)g * CPG) * HW;
    const int N = CPG * HW;
    const int t = threadIdx.x;

    float s = 0.f, ss = 0.f;
    for (int i = t; i < N; i += 512) {
        float v = xp[i];
        s += v; ss += v * v;
    }
    rs[t] = s; rq[t] = ss;
    __syncthreads();
    #pragma unroll
    for (int o = 256; o > 0; o >>= 1) {
        if (t < o) { rs[t] += rs[t + o]; rq[t] += rq[t + o]; }
        __syncthreads();
    }
    if (t < CPG) {
        const float mean = rs[0] * (1.0f / N);
        const float var  = rq[0] * (1.0f / N) - mean * mean;
        const float rinv = rsqrtf(var + EPSV);
        const int c = g * CPG + t;
        const float wc = w[c];
        g_scl[b * CC + c] = rinv * wc;
        g_sft[b * CC + c] = bgn[c] - mean * rinv * wc;
    }
}

// ------------------------------------------------------------------
// GroupNorm apply: 64n x 512c tile via smem; coalesced h^T writes
// ------------------------------------------------------------------
#define GN_SM (64 * 260 * 4)

__global__ __launch_bounds__(256) void gn_apply(const float* __restrict__ x) {
    extern __shared__ float sm[];    // [64][260]
    const int b = blockIdx.y, n0 = blockIdx.x * 64, tid = threadIdx.x;
    const float* xb = x + (size_t)b * CC * HW;
    bf16* hb = g_h + (size_t)b * HW * CC;
    const float* scl = g_scl + b * CC;
    const float* sft = g_sft + b * CC;

    #pragma unroll
    for (int ch = 0; ch < 2; ch++) {
        const int c0 = ch * 256;
        // load 256c x 64n fp32 (float4 along n), transpose into smem
        #pragma unroll
        for (int it = 0; it < 16; it++) {
            int idx = tid + it * 256;          // 0..4095
            int c  = idx >> 4;                 // 0..255
            int n4 = (idx & 15) * 4;           // 0..60
            float4 v = *(const float4*)&xb[(size_t)(c0 + c) * HW + n0 + n4];
            sm[(n4 + 0) * 260 + c] = v.x;
            sm[(n4 + 1) * 260 + c] = v.y;
            sm[(n4 + 2) * 260 + c] = v.z;
            sm[(n4 + 3) * 260 + c] = v.w;
        }
        __syncthreads();
        // scale + shift + bf16, write h^T rows coalesced
        #pragma unroll
        for (int it = 0; it < 32; it++) {
            int idx = tid + it * 256;          // 0..8191
            int n  = idx >> 7;                 // 0..63
            int cp = (idx & 127) * 2;          // 0..254
            const float s0 = scl[c0 + cp],     f0 = sft[c0 + cp];
            const float s1 = scl[c0 + cp + 1], f1 = sft[c0 + cp + 1];
            const float2 xv = *(const float2*)&sm[n * 260 + cp];
            bf162 w;
            w.x = __float2bfloat16_rn(xv.x * s0 + f0);
            w.y = __float2bfloat16_rn(xv.y * s1 + f1);
            *(bf162*)&hb[(size_t)(n0 + n) * CC + c0 + cp] = w;
        }
        __syncthreads();
    }
}

// ------------------------------------------------------------------
// tiles: 128x128x64, 4 warps (2x2), 128 threads, 2 CTAs/SM, 3-stage cp.async
// ------------------------------------------------------------------
#define STAGES 3
#define A_BYTES 16384
#define B_BYTES 16384
#define STAGE_B (A_BYTES + B_BYTES)
#define SMEM_DYN (1024 + STAGES * STAGE_B)

__device__ __forceinline__ void load_tile(uint32_t slot, const bf16* __restrict__ g,
                                          int row0, int k0, int ld, int tid) {
    #pragma unroll
    for (int c = 0; c < 8; c++) {
        int chunk = tid + c * 128;
        int r  = chunk >> 3;
        int c8 = chunk & 7;
        uint32_t off = SWZ((uint32_t)(r * 128 + c8 * 16));
        cpasync16(slot + off, g + (size_t)(row0 + r) * ld + k0 + c8 * 8);
    }
}

// B row-major [K,N] tile: 64 k-rows x 128 n-cols, 2 col-blocks of 8KB
__device__ __forceinline__ void load_tileT(uint32_t slot, const bf16* __restrict__ g,
                                           int n0, int k0, int ld, int tid) {
    #pragma unroll
    for (int c = 0; c < 8; c++) {
        int chunk = tid + c * 128;
        int r = chunk >> 4;
        int u = chunk & 15;
        uint32_t off = (uint32_t)(u >> 3) * 8192u + SWZ((uint32_t)(r * 128 + (u & 7) * 16));
        cpasync16(slot + off, g + (size_t)(k0 + r) * ld + n0 + u * 8);
    }
}

// ------------------------------------------------------------------
// generic GEMM: D = A[M,K].B[N,K]^T; EXPF: D=exp(alpha*D)
// ------------------------------------------------------------------
template <bool SCALE, bool ROWB, bool COLB, bool RESID, bool OUTBF, bool EXPF>
__global__ __launch_bounds__(128, 2) void mm_kernel(
    const bf16* __restrict__ A, int lda, const bf16* __restrict__ B, int ldb,
    void* __restrict__ Cv,
    int M, int N, int K, long sA, long sB, long sC,
    const float* __restrict__ bias, const float* __restrict__ resid, float alpha)
{
    extern __shared__ char smraw[];
    const uint32_t sb = (smem_to_u32(smraw) + 1023u) & ~1023u;

    const int tid = threadIdx.x, lane = tid & 31, wid = tid >> 5;
    const int wm = wid >> 1;
    const int wn = wid & 1;
    const int bm = blockIdx.y * 128, bn = blockIdx.x * 128, z = blockIdx.z;
    A += (size_t)z * sA;
    B += (size_t)z * sB;

    float c[4][8][4];
    #pragma unroll
    for (int i = 0; i < 4; i++)
        #pragma unroll
        for (int j = 0; j < 8; j++)
            #pragma unroll
            for (int r = 0; r < 4; r++) c[i][j][r] = 0.f;

    #pragma unroll
    for (int t = 0; t < STAGES - 1; t++) {
        load_tile(sb + t * STAGE_B, A, bm, t * 64, lda, tid);
        load_tile(sb + t * STAGE_B + A_BYTES, B, bn, t * 64, ldb, tid);
        CP_COMMIT();
    }

    const int nk = K >> 6;
    const int arow = lane & 15;
    const int akb  = (lane >> 4) * 16;
    const int brow = (lane & 7) | ((lane & 16) >> 1);
    const int bkb  = (lane & 8) << 1;

    for (int kt = 0; kt < nk; kt++) {
        CP_WAIT1();
        __syncthreads();

        const int tl = kt + STAGES - 1;
        if (tl < nk) {
            const int slot = tl % STAGES;
            load_tile(sb + slot * STAGE_B, A, bm, tl * 64, lda, tid);
            load_tile(sb + slot * STAGE_B + A_BYTES, B, bn, tl * 64, ldb, tid);
        }
        CP_COMMIT();

        const uint32_t aBase = sb + (kt % STAGES) * STAGE_B;
        const uint32_t bBase = aBase + A_BYTES;

        #pragma unroll
        for (int kb = 0; kb < 4; kb++) {
            uint32_t a[4][4];
            #pragma unroll
            for (int fm = 0; fm < 4; fm++) {
                uint32_t addr = aBase +
                    SWZ((uint32_t)((wm * 64 + fm * 16 + arow) * 128 + kb * 32 + akb));
                ldsm4(a[fm][0], a[fm][1], a[fm][2], a[fm][3], addr);
            }
            uint32_t b[4][4];
            #pragma unroll
            for (int fb = 0; fb < 4; fb++) {
                uint32_t addr = bBase +
                    SWZ((uint32_t)((wn * 64 + fb * 16 + brow) * 128 + kb * 32 + bkb));
                ldsm4(b[fb][0], b[fb][1], b[fb][2], b[fb][3], addr);
            }
            #pragma unroll
            for (int fm = 0; fm < 4; fm++)
                #pragma unroll
                for (int fn = 0; fn < 8; fn++)
                    mma_bf16(c[fm][fn],
                             a[fm][0], a[fm][1], a[fm][2], a[fm][3],
                             b[fn >> 1][(fn & 1) * 2], b[fn >> 1][(fn & 1) * 2 + 1]);
        }
    }

    // ---------------- epilogue ----------------
    const int gid = lane >> 2, tig = lane & 3;
    const float* Rb = RESID ? (resid + (size_t)z * sC) : nullptr;

    #pragma unroll
    for (int fm = 0; fm < 4; fm++) {
        const int r0 = bm + wm * 64 + fm * 16 + gid;
        float rb0 = ROWB ? bias[r0] : 0.f;
        float rb1 = ROWB ? bias[r0 + 8] : 0.f;
        #pragma unroll
        for (int fn = 0; fn < 8; fn++) {
            const int col = bn + wn * 64 + fn * 8 + 2 * tig;
            float cb0 = COLB ? bias[col] : 0.f;
            float cb1 = COLB ? bias[col + 1] : 0.f;

            float2 v0, v1;
            v0.x = c[fm][fn][0]; v0.y = c[fm][fn][1];
            v1.x = c[fm][fn][2]; v1.y = c[fm][fn][3];
            if (SCALE) { v0.x *= alpha; v0.y *= alpha; v1.x *= alpha; v1.y *= alpha; }
            if (EXPF) {
                v0.x = __expf(v0.x); v0.y = __expf(v0.y);
                v1.x = __expf(v1.x); v1.y = __expf(v1.y);
            }
            if (COLB)  { v0.x += cb0; v0.y += cb1; v1.x += cb0; v1.y += cb1; }
            if (ROWB)  { v0.x += rb0; v0.y += rb0; v1.x += rb1; v1.y += rb1; }
            if (RESID) {
                const float2 q0 = *(const float2*)&Rb[(size_t)r0 * N + col];
                const float2 q1 = *(const float2*)&Rb[(size_t)(r0 + 8) * N + col];
                v0.x += q0.x; v0.y += q0.y; v1.x += q1.x; v1.y += q1.y;
            }
            if (OUTBF) {
                bf16* Cb = (bf16*)Cv + (size_t)z * sC;
                bf162 w0, w1;
                w0.x = __float2bfloat16_rn(v0.x); w0.y = __float2bfloat16_rn(v0.y);
                w1.x = __float2bfloat16_rn(v1.x); w1.y = __float2bfloat16_rn(v1.y);
                *(bf162*)&Cb[(size_t)r0 * N + col] = w0;
                *(bf162*)&Cb[(size_t)(r0 + 8) * N + col] = w1;
            } else {
                float* Cb = (float*)Cv + (size_t)z * sC;
                *(float2*)&Cb[(size_t)r0 * N + col] = v0;
                *(float2*)&Cb[(size_t)(r0 + 8) * N + col] = v1;
            }
        }
    }
}

// ------------------------------------------------------------------
// AV: O[i,c] = (sum_j P[i,j] V[j,c]) / (sum_j P[i,j])
// A = unnormalized probs (bf16), B = V^T via ldmatrix.trans.
// Row sums accumulated from A fragments, normalized in epilogue.
// ------------------------------------------------------------------
__global__ __launch_bounds__(128, 2) void av_kernel(
    const bf16* __restrict__ A, int lda, const bf16* __restrict__ B, int ldb,
    bf16* __restrict__ C, int N, int K, long sA, long sB, long sC)
{
    extern __shared__ char smraw[];
    const uint32_t sb = (smem_to_u32(smraw) + 1023u) & ~1023u;

    const int tid = threadIdx.x, lane = tid & 31, wid = tid >> 5;
    const int wm = wid >> 1;
    const int wn = wid & 1;
    const int bm = blockIdx.y * 128, bn = blockIdx.x * 128, z = blockIdx.z;
    A += (size_t)z * sA;
    B += (size_t)z * sB;

    float c[4][8][4];
    #pragma unroll
    for (int i = 0; i < 4; i++)
        #pragma unroll
        for (int j = 0; j < 8; j++)
            #pragma unroll
            for (int r = 0; r < 4; r++) c[i][j][r] = 0.f;
    float rs[4][2];
    #pragma unroll
    for (int i = 0; i < 4; i++) { rs[i][0] = 0.f; rs[i][1] = 0.f; }

    #pragma unroll
    for (int t = 0; t < STAGES - 1; t++) {
        load_tile(sb + t * STAGE_B, A, bm, t * 64, lda, tid);
        load_tileT(sb + t * STAGE_B + A_BYTES, B, bn, t * 64, ldb, tid);
        CP_COMMIT();
    }

    const int nk = K >> 6;
    const int arow = lane & 15;
    const int akb  = (lane >> 4) * 16;
    const int trow = lane & 15;
    const int tnb  = (lane >> 4) * 16;

    for (int kt = 0; kt < nk; kt++) {
        CP_WAIT1();
        __syncthreads();

        const int tl = kt + STAGES - 1;
        if (tl < nk) {
            const int slot = tl % STAGES;
            load_tile(sb + slot * STAGE_B, A, bm, tl * 64, lda, tid);
            load_tileT(sb + slot * STAGE_B + A_BYTES, B, bn, tl * 64, ldb, tid);
        }
        CP_COMMIT();

        const uint32_t aBase = sb + (kt % STAGES) * STAGE_B;
        const uint32_t bBase = aBase + A_BYTES;

        #pragma unroll
        for (int kb = 0; kb < 4; kb++) {
            uint32_t a[4][4];
            #pragma unroll
            for (int fm = 0; fm < 4; fm++) {
                uint32_t addr = aBase +
                    SWZ((uint32_t)((wm * 64 + fm * 16 + arow) * 128 + kb * 32 + akb));
                ldsm4(a[fm][0], a[fm][1], a[fm][2], a[fm][3], addr);
            }
            #pragma unroll
            for (int fm = 0; fm < 4; fm++) {
                float2 t0 = __bfloat1622float2(*(bf162*)&a[fm][0]);
                float2 t1 = __bfloat1622float2(*(bf162*)&a[fm][1]);
                float2 t2 = __bfloat1622float2(*(bf162*)&a[fm][2]);
                float2 t3 = __bfloat1622float2(*(bf162*)&a[fm][3]);
                rs[fm][0] += (t0.x + t0.y) + (t2.x + t2.y);
                rs[fm][1] += (t1.x + t1.y) + (t3.x + t3.y);
            }
            uint32_t b[4][4];
            #pragma unroll
            for (int fb = 0; fb < 4; fb++) {
                uint32_t addr = bBase + (uint32_t)wn * 8192u +
                    SWZ((uint32_t)((kb * 16 + trow) * 128 + fb * 32 + tnb));
                ldsm4t(b[fb][0], b[fb][1], b[fb][2], b[fb][3], addr);
            }
            #pragma unroll
            for (int fm = 0; fm < 4; fm++)
                #pragma unroll
                for (int fn = 0; fn < 8; fn++)
                    mma_bf16(c[fm][fn],
                             a[fm][0], a[fm][1], a[fm][2], a[fm][3],
                             b[fn >> 1][(fn & 1) * 2], b[fn >> 1][(fn & 1) * 2 + 1]);
        }
    }

    // ---------------- epilogue: normalize, bf16 out ----------------
    const int gid = lane >> 2, tig = lane & 3;
    bf16* Cb = C + (size_t)z * sC;

    #pragma unroll
    for (int fm = 0; fm < 4; fm++) {
        float s0 = rs[fm][0];
        s0 += __shfl_xor_sync(0xffffffffu, s0, 1);
        s0 += __shfl_xor_sync(0xffffffffu, s0, 2);
        float s1 = rs[fm][1];
        s1 += __shfl_xor_sync(0xffffffffu, s1, 1);
        s1 += __shfl_xor_sync(0xffffffffu, s1, 2);
        const float inv0 = 1.0f / s0;
        const float inv1 = 1.0f / s1;
        const int r0 = bm + wm * 64 + fm * 16 + gid;
        #pragma unroll
        for (int fn = 0; fn < 8; fn++) {
            const int col = bn + wn * 64 + fn * 8 + 2 * tig;
            bf162 w0, w1;
            w0.x = __float2bfloat16_rn(c[fm][fn][0] * inv0);
            w0.y = __float2bfloat16_rn(c[fm][fn][1] * inv0);
            w1.x = __float2bfloat16_rn(c[fm][fn][2] * inv1);
            w1.y = __float2bfloat16_rn(c[fm][fn][3] * inv1);
            *(bf162*)&Cb[(size_t)r0 * N + col] = w0;
            *(bf162*)&Cb[(size_t)(r0 + 8) * N + col] = w1;
        }
    }
}

// ------------------------------------------------------------------
// launch
// ------------------------------------------------------------------
extern "C" void kernel_launch(void* const* d_in, const int* in_sizes, int n_in,
                              void* d_out, int out_size) {
    const float* x   = (const float*)d_in[0];
    const float* gnw = (const float*)d_in[1];
    const float* gnb = (const float*)d_in[2];
    const float* qw  = (const float*)d_in[3];
    const float* qb  = (const float*)d_in[4];
    const float* kw  = (const float*)d_in[5];
    const float* kb  = (const float*)d_in[6];
    const float* vw  = (const float*)d_in[7];
    const float* vb  = (const float*)d_in[8];
    const float* pw  = (const float*)d_in[9];
    const float* pb  = (const float*)d_in[10];
    float* out = (float*)d_out;

    bf16 *h, *qkv, *o, *p, *wb;
    float* qkvbv;
    cudaGetSymbolAddress((void**)&h,   g_h);
    cudaGetSymbolAddress((void**)&qkv, g_qkv);
    cudaGetSymbolAddress((void**)&o,   g_o);
    cudaGetSymbolAddress((void**)&p,   g_p);
    cudaGetSymbolAddress((void**)&wb,  g_w);
    cudaGetSymbolAddress((void**)&qkvbv, g_qkvb);
    bf16* qkvwb = wb;                         // [Wq;Wk;Wv] contiguous
    bf16* pwb   = wb + 3 * (size_t)CC * CC;

    cudaFuncSetAttribute(mm_kernel<false, false, true,  false, true,  false>, cudaFuncAttributeMaxDynamicSharedMemorySize, SMEM_DYN);
    cudaFuncSetAttribute(mm_kernel<true,  false, false, false, true,  true >, cudaFuncAttributeMaxDynamicSharedMemorySize, SMEM_DYN);
    cudaFuncSetAttribute(mm_kernel<false, true,  false, true,  false, false>, cudaFuncAttributeMaxDynamicSharedMemorySize, SMEM_DYN);
    cudaFuncSetAttribute(av_kernel, cudaFuncAttributeMaxDynamicSharedMemorySize, SMEM_DYN);
    cudaFuncSetAttribute(gn_apply,  cudaFuncAttributeMaxDynamicSharedMemorySize, GN_SM);

    const long sNC  = (long)HW * CC;
    const long sNC3 = (long)HW * 3 * CC;
    const long sCN  = (long)CC * HW;
    const long sNN  = (long)HW * HW;
    const float scale = 0.044194173824159216f;   // 512^-0.5

    // 0. weights -> bf16, concat qkv bias
    cvtw_kernel<<<(4 * CC * CC + 255) / 256, 256>>>(qw, kw, vw, pw, qb, kb, vb);

    // 1. GroupNorm: stats then coalesced apply -> h^T [b, n, c] bf16
    gn_stats<<<BB * GG, 512>>>(x, gnw, gnb);
    gn_apply<<<dim3(HW / 64, BB), 256, GN_SM>>>(x);

    // 2. fused qkv [b, n, 1536]: M=HW, N=1536, K=CC; +col bias
    dim3 gQKV(1536 / 128, HW / 128, BB);
    mm_kernel<false, false, true, false, true, false><<<gQKV, 128, SMEM_DYN>>>(
        h, CC, qkvwb, CC, qkv, HW, 3 * CC, CC, sNC, 0, sNC3, qkvbv, nullptr, 1.f);

    // 3. probs = exp(q.k * scale), unnormalized bf16
    dim3 gS(HW / 128, HW / 128, BB);
    mm_kernel<true, false, false, false, true, true><<<gS, 128, SMEM_DYN>>>(
        qkv, 3 * CC, qkv + CC, 3 * CC, p, HW, HW, CC, sNC3, sNC3, sNN,
        nullptr, nullptr, scale);

    // 4. AV + normalize: o^T [b, i, c]
    dim3 gO(CC / 128, HW / 128, BB);
    av_kernel<<<gO, 128, SMEM_DYN>>>(
        p, HW, qkv + 2 * CC, 3 * CC, o, CC, HW, sNN, sNC3, sNC);

    // 5. out [b, c, n]: M=CC, N=HW, K=CC; A=Wp, B=o^T; +row bias + residual; fp32
    dim3 gP(HW / 128, CC / 128, BB);
    mm_kernel<false, true, false, true, false, false><<<gP, 128, SMEM_DYN>>>(
        pwb, CC, o, CC, out, CC, HW, CC, 0, sNC, sCN, pb, x, 1.f);
}

// round 13
// speedup vs baseline: 1.2004x; 1.0715x over previous
#include <cuda_runtime.h>
#include <cuda_bf16.h>
#include <cstdint>
#include <math.h>

#define CC   512
#define HW   4096
#define BB   4
#define GG   32
#define CPG  16
#define EPSV 1e-5f

typedef __nv_bfloat16  bf16;
typedef __nv_bfloat162 bf162;

// ------------------------------------------------------------------
// scratch
// ------------------------------------------------------------------
__device__ bf16  g_h[(size_t)BB * HW * CC];        // h^T    [b, n, c]
__device__ bf16  g_qkv[(size_t)BB * HW * 3 * CC];  // q|k|v^T packed [b, n, 1536]
__device__ bf16  g_o[(size_t)BB * HW * CC];        // o^T    [b, n, c]
__device__ bf16  g_p[(size_t)BB * HW * HW];        // unnormalized probs e^s (bf16)
__device__ bf16  g_w[4][(size_t)CC * CC];          // bf16 weights q,k,v (contig) + p
__device__ float g_qkvb[3 * CC];                   // concat(q_b, k_b, v_b)
__device__ float g_scl[BB * CC];                   // GN per-channel scale
__device__ float g_sft[BB * CC];                   // GN per-channel shift

// dataflow counters
__device__ unsigned g_cQKV[BB * 32];   // per (b, n-block): 12 col-tiles
__device__ unsigned g_cTot[BB];        // per b: 384 qkv tiles
__device__ unsigned g_cS[BB * 32];     // per (b, i-block): 32 j-tiles
__device__ unsigned g_cAV[BB * 32];    // per (b, i-block): 4 c-tiles

// ------------------------------------------------------------------
// helpers
// ------------------------------------------------------------------
__device__ __forceinline__ uint32_t smem_to_u32(const void* p) {
    uint32_t a;
    asm("{ .reg .u64 t; cvta.to.shared.u64 t, %1; cvt.u32.u64 %0, t; }"
        : "=r"(a) : "l"(p));
    return a;
}

#define SWZ(o) ((o) ^ (((o) >> 3) & 0x70))

__device__ __forceinline__ void cpasync16(uint32_t dst, const void* src) {
    asm volatile("cp.async.cg.shared.global [%0], [%1], 16;" :: "r"(dst), "l"(src));
}
#define CP_COMMIT() asm volatile("cp.async.commit_group;" ::: "memory")
#define CP_WAIT1()  asm volatile("cp.async.wait_group 1;" ::: "memory")

__device__ __forceinline__ void ldsm4(uint32_t& r0, uint32_t& r1, uint32_t& r2,
                                      uint32_t& r3, uint32_t addr) {
    asm volatile("ldmatrix.sync.aligned.m8n8.x4.shared.b16 {%0,%1,%2,%3}, [%4];"
                 : "=r"(r0), "=r"(r1), "=r"(r2), "=r"(r3) : "r"(addr));
}

__device__ __forceinline__ void ldsm4t(uint32_t& r0, uint32_t& r1, uint32_t& r2,
                                       uint32_t& r3, uint32_t addr) {
    asm volatile("ldmatrix.sync.aligned.m8n8.x4.trans.shared.b16 {%0,%1,%2,%3}, [%4];"
                 : "=r"(r0), "=r"(r1), "=r"(r2), "=r"(r3) : "r"(addr));
}

__device__ __forceinline__ void mma_bf16(float c[4], uint32_t a0, uint32_t a1,
                                         uint32_t a2, uint32_t a3,
                                         uint32_t b0, uint32_t b1) {
    asm volatile(
        "mma.sync.aligned.m16n8k16.row.col.f32.bf16.bf16.f32 "
        "{%0,%1,%2,%3}, {%4,%5,%6,%7}, {%8,%9}, {%0,%1,%2,%3};"
        : "+f"(c[0]), "+f"(c[1]), "+f"(c[2]), "+f"(c[3])
        : "r"(a0), "r"(a1), "r"(a2), "r"(a3), "r"(b0), "r"(b1));
}

__device__ __forceinline__ unsigned ld_acq(const unsigned* p) {
    unsigned v;
    asm volatile("ld.acquire.gpu.u32 %0, [%1];" : "=r"(v) : "l"(p));
    return v;
}

// all threads call; tid0 spins; barrier orders the block after the acquire
__device__ __forceinline__ void wait_ge(const unsigned* p, unsigned tgt) {
    if (threadIdx.x == 0) {
        while (ld_acq(p) < tgt) __nanosleep(64);
    }
    __syncthreads();
}

// all threads call after their global stores
__device__ __forceinline__ void signal1(unsigned* p) {
    __threadfence();
    __syncthreads();
    if (threadIdx.x == 0) atomicAdd(p, 1u);
}
__device__ __forceinline__ void signal2(unsigned* p0, unsigned* p1) {
    __threadfence();
    __syncthreads();
    if (threadIdx.x == 0) { atomicAdd(p0, 1u); atomicAdd(p1, 1u); }
}

// ------------------------------------------------------------------
// weights -> bf16; qkv bias; zero counters (runs first every call)
// ------------------------------------------------------------------
__global__ __launch_bounds__(256) void cvtw_kernel(const float* __restrict__ q,
                                                   const float* __restrict__ k,
                                                   const float* __restrict__ v,
                                                   const float* __restrict__ p,
                                                   const float* __restrict__ qb,
                                                   const float* __restrict__ kb,
                                                   const float* __restrict__ vb) {
    const int n = CC * CC;
    int i = blockIdx.x * 256 + threadIdx.x;
    if (i < 3 * CC)
        g_qkvb[i] = (i < CC) ? qb[i] : (i < 2 * CC) ? kb[i - CC] : vb[i - 2 * CC];
    if (i < BB * 32) { g_cQKV[i] = 0u; g_cS[i] = 0u; g_cAV[i] = 0u; }
    if (i < BB) g_cTot[i] = 0u;
    if (i >= 4 * n) return;
    const int seg = i / n, j = i % n;
    const float* src = (seg == 0) ? q : (seg == 1) ? k : (seg == 2) ? v : p;
    g_w[seg][j] = __float2bfloat16_rn(src[j]);
}

// ------------------------------------------------------------------
// GroupNorm stats + apply (as R11)
// ------------------------------------------------------------------
__global__ __launch_bounds__(512) void gn_stats(const float* __restrict__ x,
                                                const float* __restrict__ w,
                                                const float* __restrict__ bgn) {
    __shared__ float rs[512], rq[512];
    const int bg = blockIdx.x;
    const int b = bg / GG, g = bg % GG;
    const float* xp = x + ((size_t)b * CC + (size_t)g * CPG) * HW;
    const int N = CPG * HW;
    const int t = threadIdx.x;

    float s = 0.f, ss = 0.f;
    for (int i = t; i < N; i += 512) {
        float v = xp[i];
        s += v; ss += v * v;
    }
    rs[t] = s; rq[t] = ss;
    __syncthreads();
    #pragma unroll
    for (int o = 256; o > 0; o >>= 1) {
        if (t < o) { rs[t] += rs[t + o]; rq[t] += rq[t + o]; }
        __syncthreads();
    }
    if (t < CPG) {
        const float mean = rs[0] * (1.0f / N);
        const float var  = rq[0] * (1.0f / N) - mean * mean;
        const float rinv = rsqrtf(var + EPSV);
        const int c = g * CPG + t;
        const float wc = w[c];
        g_scl[b * CC + c] = rinv * wc;
        g_sft[b * CC + c] = bgn[c] - mean * rinv * wc;
    }
}

#define GN_SM (64 * 260 * 4)

__global__ __launch_bounds__(256) void gn_apply(const float* __restrict__ x) {
    extern __shared__ float sm[];
    const int b = blockIdx.y, n0 = blockIdx.x * 64, tid = threadIdx.x;
    const float* xb = x + (size_t)b * CC * HW;
    bf16* hb = g_h + (size_t)b * HW * CC;
    const float* scl = g_scl + b * CC;
    const float* sft = g_sft + b * CC;

    #pragma unroll
    for (int ch = 0; ch < 2; ch++) {
        const int c0 = ch * 256;
        #pragma unroll
        for (int it = 0; it < 16; it++) {
            int idx = tid + it * 256;
            int c  = idx >> 4;
            int n4 = (idx & 15) * 4;
            float4 v = *(const float4*)&xb[(size_t)(c0 + c) * HW + n0 + n4];
            sm[(n4 + 0) * 260 + c] = v.x;
            sm[(n4 + 1) * 260 + c] = v.y;
            sm[(n4 + 2) * 260 + c] = v.z;
            sm[(n4 + 3) * 260 + c] = v.w;
        }
        __syncthreads();
        #pragma unroll
        for (int it = 0; it < 32; it++) {
            int idx = tid + it * 256;
            int n  = idx >> 7;
            int cp = (idx & 127) * 2;
            const float s0 = scl[c0 + cp],     f0 = sft[c0 + cp];
            const float s1 = scl[c0 + cp + 1], f1 = sft[c0 + cp + 1];
            const float2 xv = *(const float2*)&sm[n * 260 + cp];
            bf162 w;
            w.x = __float2bfloat16_rn(xv.x * s0 + f0);
            w.y = __float2bfloat16_rn(xv.y * s1 + f1);
            *(bf162*)&hb[(size_t)(n0 + n) * CC + c0 + cp] = w;
        }
        __syncthreads();
    }
}

// ------------------------------------------------------------------
// GEMM machinery (128x128x64, 4 warps, 3-stage cp.async)
// ------------------------------------------------------------------
#define STAGES 3
#define A_BYTES 16384
#define B_BYTES 16384
#define STAGE_B (A_BYTES + B_BYTES)
#define SMEM_DYN (1024 + STAGES * STAGE_B)

__device__ __forceinline__ void load_tile(uint32_t slot, const bf16* __restrict__ g,
                                          int row0, int k0, int ld, int tid) {
    #pragma unroll
    for (int c = 0; c < 8; c++) {
        int chunk = tid + c * 128;
        int r  = chunk >> 3;
        int c8 = chunk & 7;
        uint32_t off = SWZ((uint32_t)(r * 128 + c8 * 16));
        cpasync16(slot + off, g + (size_t)(row0 + r) * ld + k0 + c8 * 8);
    }
}

__device__ __forceinline__ void load_tileT(uint32_t slot, const bf16* __restrict__ g,
                                           int n0, int k0, int ld, int tid) {
    #pragma unroll
    for (int c = 0; c < 8; c++) {
        int chunk = tid + c * 128;
        int r = chunk >> 4;
        int u = chunk & 15;
        uint32_t off = (uint32_t)(u >> 3) * 8192u + SWZ((uint32_t)(r * 128 + (u & 7) * 16));
        cpasync16(slot + off, g + (size_t)(k0 + r) * ld + n0 + u * 8);
    }
}

template <bool SCALE, bool ROWB, bool COLB, bool RESID, bool OUTBF, bool EXPF>
__device__ __forceinline__ void mm_body(
    const bf16* __restrict__ A, int lda, const bf16* __restrict__ B, int ldb,
    void* __restrict__ Cv, int N, int K,
    const float* __restrict__ bias, const float* __restrict__ resid, float alpha,
    int bm, int bn, uint32_t sb)
{
    const int tid = threadIdx.x, lane = tid & 31, wid = tid >> 5;
    const int wm = wid >> 1;
    const int wn = wid & 1;

    float c[4][8][4];
    #pragma unroll
    for (int i = 0; i < 4; i++)
        #pragma unroll
        for (int j = 0; j < 8; j++)
            #pragma unroll
            for (int r = 0; r < 4; r++) c[i][j][r] = 0.f;

    #pragma unroll
    for (int t = 0; t < STAGES - 1; t++) {
        load_tile(sb + t * STAGE_B, A, bm, t * 64, lda, tid);
        load_tile(sb + t * STAGE_B + A_BYTES, B, bn, t * 64, ldb, tid);
        CP_COMMIT();
    }

    const int nk = K >> 6;
    const int arow = lane & 15;
    const int akb  = (lane >> 4) * 16;
    const int brow = (lane & 7) | ((lane & 16) >> 1);
    const int bkb  = (lane & 8) << 1;

    for (int kt = 0; kt < nk; kt++) {
        CP_WAIT1();
        __syncthreads();

        const int tl = kt + STAGES - 1;
        if (tl < nk) {
            const int slot = tl % STAGES;
            load_tile(sb + slot * STAGE_B, A, bm, tl * 64, lda, tid);
            load_tile(sb + slot * STAGE_B + A_BYTES, B, bn, tl * 64, ldb, tid);
        }
        CP_COMMIT();

        const uint32_t aBase = sb + (kt % STAGES) * STAGE_B;
        const uint32_t bBase = aBase + A_BYTES;

        #pragma unroll
        for (int kb = 0; kb < 4; kb++) {
            uint32_t a[4][4];
            #pragma unroll
            for (int fm = 0; fm < 4; fm++) {
                uint32_t addr = aBase +
                    SWZ((uint32_t)((wm * 64 + fm * 16 + arow) * 128 + kb * 32 + akb));
                ldsm4(a[fm][0], a[fm][1], a[fm][2], a[fm][3], addr);
            }
            uint32_t b[4][4];
            #pragma unroll
            for (int fb = 0; fb < 4; fb++) {
                uint32_t addr = bBase +
                    SWZ((uint32_t)((wn * 64 + fb * 16 + brow) * 128 + kb * 32 + bkb));
                ldsm4(b[fb][0], b[fb][1], b[fb][2], b[fb][3], addr);
            }
            #pragma unroll
            for (int fm = 0; fm < 4; fm++)
                #pragma unroll
                for (int fn = 0; fn < 8; fn++)
                    mma_bf16(c[fm][fn],
                             a[fm][0], a[fm][1], a[fm][2], a[fm][3],
                             b[fn >> 1][(fn & 1) * 2], b[fn >> 1][(fn & 1) * 2 + 1]);
        }
    }

    const int gid = lane >> 2, tig = lane & 3;

    #pragma unroll
    for (int fm = 0; fm < 4; fm++) {
        const int r0 = bm + wm * 64 + fm * 16 + gid;
        float rb0 = ROWB ? bias[r0] : 0.f;
        float rb1 = ROWB ? bias[r0 + 8] : 0.f;
        #pragma unroll
        for (int fn = 0; fn < 8; fn++) {
            const int col = bn + wn * 64 + fn * 8 + 2 * tig;
            float cb0 = COLB ? bias[col] : 0.f;
            float cb1 = COLB ? bias[col + 1] : 0.f;

            float2 v0, v1;
            v0.x = c[fm][fn][0]; v0.y = c[fm][fn][1];
            v1.x = c[fm][fn][2]; v1.y = c[fm][fn][3];
            if (SCALE) { v0.x *= alpha; v0.y *= alpha; v1.x *= alpha; v1.y *= alpha; }
            if (EXPF) {
                v0.x = __expf(v0.x); v0.y = __expf(v0.y);
                v1.x = __expf(v1.x); v1.y = __expf(v1.y);
            }
            if (COLB)  { v0.x += cb0; v0.y += cb1; v1.x += cb0; v1.y += cb1; }
            if (ROWB)  { v0.x += rb0; v0.y += rb0; v1.x += rb1; v1.y += rb1; }
            if (RESID) {
                const float2 q0 = *(const float2*)&resid[(size_t)r0 * N + col];
                const float2 q1 = *(const float2*)&resid[(size_t)(r0 + 8) * N + col];
                v0.x += q0.x; v0.y += q0.y; v1.x += q1.x; v1.y += q1.y;
            }
            if (OUTBF) {
                bf16* Cb = (bf16*)Cv;
                bf162 w0, w1;
                w0.x = __float2bfloat16_rn(v0.x); w0.y = __float2bfloat16_rn(v0.y);
                w1.x = __float2bfloat16_rn(v1.x); w1.y = __float2bfloat16_rn(v1.y);
                *(bf162*)&Cb[(size_t)r0 * N + col] = w0;
                *(bf162*)&Cb[(size_t)(r0 + 8) * N + col] = w1;
            } else {
                float* Cb = (float*)Cv;
                *(float2*)&Cb[(size_t)r0 * N + col] = v0;
                *(float2*)&Cb[(size_t)(r0 + 8) * N + col] = v1;
            }
        }
    }
}

__device__ __forceinline__ void av_body(
    const bf16* __restrict__ A, int lda, const bf16* __restrict__ B, int ldb,
    bf16* __restrict__ C, int N, int K, int bm, int bn, uint32_t sb)
{
    const int tid = threadIdx.x, lane = tid & 31, wid = tid >> 5;
    const int wm = wid >> 1;
    const int wn = wid & 1;

    float c[4][8][4];
    #pragma unroll
    for (int i = 0; i < 4; i++)
        #pragma unroll
        for (int j = 0; j < 8; j++)
            #pragma unroll
            for (int r = 0; r < 4; r++) c[i][j][r] = 0.f;
    float rs[4][2];
    #pragma unroll
    for (int i = 0; i < 4; i++) { rs[i][0] = 0.f; rs[i][1] = 0.f; }

    #pragma unroll
    for (int t = 0; t < STAGES - 1; t++) {
        load_tile(sb + t * STAGE_B, A, bm, t * 64, lda, tid);
        load_tileT(sb + t * STAGE_B + A_BYTES, B, bn, t * 64, ldb, tid);
        CP_COMMIT();
    }

    const int nk = K >> 6;
    const int arow = lane & 15;
    const int akb  = (lane >> 4) * 16;
    const int trow = lane & 15;
    const int tnb  = (lane >> 4) * 16;

    for (int kt = 0; kt < nk; kt++) {
        CP_WAIT1();
        __syncthreads();

        const int tl = kt + STAGES - 1;
        if (tl < nk) {
            const int slot = tl % STAGES;
            load_tile(sb + slot * STAGE_B, A, bm, tl * 64, lda, tid);
            load_tileT(sb + slot * STAGE_B + A_BYTES, B, bn, tl * 64, ldb, tid);
        }
        CP_COMMIT();

        const uint32_t aBase = sb + (kt % STAGES) * STAGE_B;
        const uint32_t bBase = aBase + A_BYTES;

        #pragma unroll
        for (int kb = 0; kb < 4; kb++) {
            uint32_t a[4][4];
            #pragma unroll
            for (int fm = 0; fm < 4; fm++) {
                uint32_t addr = aBase +
                    SWZ((uint32_t)((wm * 64 + fm * 16 + arow) * 128 + kb * 32 + akb));
                ldsm4(a[fm][0], a[fm][1], a[fm][2], a[fm][3], addr);
            }
            #pragma unroll
            for (int fm = 0; fm < 4; fm++) {
                float2 t0 = __bfloat1622float2(*(bf162*)&a[fm][0]);
                float2 t1 = __bfloat1622float2(*(bf162*)&a[fm][1]);
                float2 t2 = __bfloat1622float2(*(bf162*)&a[fm][2]);
                float2 t3 = __bfloat1622float2(*(bf162*)&a[fm][3]);
                rs[fm][0] += (t0.x + t0.y) + (t2.x + t2.y);
                rs[fm][1] += (t1.x + t1.y) + (t3.x + t3.y);
            }
            uint32_t b[4][4];
            #pragma unroll
            for (int fb = 0; fb < 4; fb++) {
                uint32_t addr = bBase + (uint32_t)wn * 8192u +
                    SWZ((uint32_t)((kb * 16 + trow) * 128 + fb * 32 + tnb));
                ldsm4t(b[fb][0], b[fb][1], b[fb][2], b[fb][3], addr);
            }
            #pragma unroll
            for (int fm = 0; fm < 4; fm++)
                #pragma unroll
                for (int fn = 0; fn < 8; fn++)
                    mma_bf16(c[fm][fn],
                             a[fm][0], a[fm][1], a[fm][2], a[fm][3],
                             b[fn >> 1][(fn & 1) * 2], b[fn >> 1][(fn & 1) * 2 + 1]);
        }
    }

    const int gid = lane >> 2, tig = lane & 3;

    #pragma unroll
    for (int fm = 0; fm < 4; fm++) {
        float s0 = rs[fm][0];
        s0 += __shfl_xor_sync(0xffffffffu, s0, 1);
        s0 += __shfl_xor_sync(0xffffffffu, s0, 2);
        float s1 = rs[fm][1];
        s1 += __shfl_xor_sync(0xffffffffu, s1, 1);
        s1 += __shfl_xor_sync(0xffffffffu, s1, 2);
        const float inv0 = 1.0f / s0;
        const float inv1 = 1.0f / s1;
        const int r0 = bm + wm * 64 + fm * 16 + gid;
        #pragma unroll
        for (int fn = 0; fn < 8; fn++) {
            const int col = bn + wn * 64 + fn * 8 + 2 * tig;
            bf162 w0, w1;
            w0.x = __float2bfloat16_rn(c[fm][fn][0] * inv0);
            w0.y = __float2bfloat16_rn(c[fm][fn][1] * inv0);
            w1.x = __float2bfloat16_rn(c[fm][fn][2] * inv1);
            w1.y = __float2bfloat16_rn(c[fm][fn][3] * inv1);
            *(bf162*)&C[(size_t)r0 * N + col] = w0;
            *(bf162*)&C[(size_t)(r0 + 8) * N + col] = w1;
        }
    }
}

// ------------------------------------------------------------------
// uber kernel: qkv | scores | av | proj in one launch, spin-wait deps
// ------------------------------------------------------------------
#define QKV_END  (384 * BB)                 // 1536
#define S_END    (QKV_END + 1024 * BB)      // 5632
#define AV_END   (S_END + 128 * BB)         // 6144
#define PJ_END   (AV_END + 128 * BB)        // 6656

__global__ __launch_bounds__(128, 2) void uber_kernel(
    const float* __restrict__ x, float* __restrict__ out,
    const float* __restrict__ pbias)
{
    extern __shared__ char smraw[];
    const uint32_t sb = (smem_to_u32(smraw) + 1023u) & ~1023u;
    const int bid = blockIdx.x;
    const float scale = 0.044194173824159216f;

    const long sNC  = (long)HW * CC;
    const long sNC3 = (long)HW * 3 * CC;
    const long sCN  = (long)CC * HW;
    const long sNN  = (long)HW * HW;

    if (bid < QKV_END) {
        const int b = bid / 384, r = bid % 384;
        const int nb = r / 12, cb = r % 12;          // n-block, col-block
        mm_body<false, false, true, false, true, false>(
            g_h + (size_t)b * sNC, CC, g_w[0], CC,
            g_qkv + (size_t)b * sNC3, 3 * CC, CC,
            g_qkvb, nullptr, 1.f, nb * 128, cb * 128, sb);
        signal2(&g_cQKV[b * 32 + nb], &g_cTot[b]);
    } else if (bid < S_END) {
        const int idx = bid - QKV_END;
        const int b = idx / 1024, r = idx % 1024;
        const int i = r / 32, j = r % 32;
        wait_ge(&g_cQKV[b * 32 + i], 12);
        wait_ge(&g_cQKV[b * 32 + j], 12);
        const bf16* qkvb = g_qkv + (size_t)b * sNC3;
        mm_body<true, false, false, false, true, true>(
            qkvb, 3 * CC, qkvb + CC, 3 * CC,
            g_p + (size_t)b * sNN, HW, CC,
            nullptr, nullptr, scale, i * 128, j * 128, sb);
        signal1(&g_cS[b * 32 + i]);
    } else if (bid < AV_END) {
        const int idx = bid - S_END;
        const int b = idx / 128, r = idx % 128;
        const int i = r / 4, cb = r % 4;
        wait_ge(&g_cTot[b], 384);                    // all of v ready
        wait_ge(&g_cS[b * 32 + i], 32);              // full prob rows
        av_body(
            g_p + (size_t)b * sNN, HW,
            g_qkv + (size_t)b * sNC3 + 2 * CC, 3 * CC,
            g_o + (size_t)b * sNC, CC, HW, i * 128, cb * 128, sb);
        signal1(&g_cAV[b * 32 + i]);
    } else {
        const int idx = bid - AV_END;
        const int b = idx / 128, r = idx % 128;
        const int nb = r / 4, cb = r % 4;
        wait_ge(&g_cAV[b * 32 + nb], 4);
        mm_body<false, true, false, true, false, false>(
            g_w[3], CC, g_o + (size_t)b * sNC, CC,
            out + (size_t)b * sCN, HW, CC,
            pbias, x + (size_t)b * sCN, 1.f, cb * 128, nb * 128, sb);
    }
}

// ------------------------------------------------------------------
// launch
// ------------------------------------------------------------------
extern "C" void kernel_launch(void* const* d_in, const int* in_sizes, int n_in,
                              void* d_out, int out_size) {
    const float* x   = (const float*)d_in[0];
    const float* gnw = (const float*)d_in[1];
    const float* gnb = (const float*)d_in[2];
    const float* qw  = (const float*)d_in[3];
    const float* qb  = (const float*)d_in[4];
    const float* kw  = (const float*)d_in[5];
    const float* kb  = (const float*)d_in[6];
    const float* vw  = (const float*)d_in[7];
    const float* vb  = (const float*)d_in[8];
    const float* pw  = (const float*)d_in[9];
    const float* pb  = (const float*)d_in[10];
    float* out = (float*)d_out;

    cudaFuncSetAttribute(uber_kernel, cudaFuncAttributeMaxDynamicSharedMemorySize, SMEM_DYN);
    cudaFuncSetAttribute(gn_apply,    cudaFuncAttributeMaxDynamicSharedMemorySize, GN_SM);

    // 0. weights -> bf16, bias concat, counter reset
    cvtw_kernel<<<(4 * CC * CC + 255) / 256, 256>>>(qw, kw, vw, pw, qb, kb, vb);

    // 1. GroupNorm
    gn_stats<<<BB * GG, 512>>>(x, gnw, gnb);
    gn_apply<<<dim3(HW / 64, BB), 256, GN_SM>>>(x);

    // 2-5. fused qkv -> scores(exp) -> AV(normalize) -> proj(+residual)
    uber_kernel<<<PJ_END, 128, SMEM_DYN>>>(x, out, pb);
}